// round 2
// baseline (speedup 1.0000x reference)
#include <cuda_runtime.h>

// Problem shape (fixed by the dataset): A [B=256, d=512, d=512] fp32,
// mask [n_regimes=16, d=512] fp32, regimes [B] int32 (JAX x64 disabled).
// Output: 1 float.
#define D 512
#define D4 (D / 4)          // 128 float4 groups per row
#define ROWS_PER_BLK 64     // 8 row-chunks per batch

__device__ double g_loss;

__global__ void k_zero() { g_loss = 0.0; }

__global__ void __launch_bounds__(256, 8)
k_reduce(const float* __restrict__ A,
         const float* __restrict__ mask,
         const int* __restrict__ regimes,
         int n_regimes) {
    const int b = blockIdx.y;
    const int e = regimes[b];
    const bool valid = (e < n_regimes);
    int ec = e < 0 ? 0 : (e >= n_regimes ? n_regimes - 1 : e);

    __shared__ float4 smask[D4];
    const int tid = threadIdx.x;
    if (tid < D4) {
        float4 m = reinterpret_cast<const float4*>(mask + (long long)ec * D)[tid];
        if (!valid) m = make_float4(0.f, 0.f, 0.f, 0.f);
        smask[tid] = m;
    }
    __syncthreads();

    const int j4   = tid & (D4 - 1);   // which float4 column group
    const int rsub = tid >> 7;         // 0 or 1: row interleave within block
    const float4 m = smask[j4];
    const bool live = (m.x != 0.f) || (m.y != 0.f) || (m.z != 0.f) || (m.w != 0.f);

    float acc = 0.f;
    if (live) {
        const float* base = A + ((long long)b * D + (long long)blockIdx.x * ROWS_PER_BLK + rsub) * D;
        #pragma unroll 4
        for (int i = 0; i < ROWS_PER_BLK; i += 2) {
            float4 a = reinterpret_cast<const float4*>(base + (long long)i * D)[j4];
            acc += a.x * m.x + a.y * m.y + a.z * m.z + a.w * m.w;
        }
    }

    // block reduction: warp shuffle then cross-warp
    #pragma unroll
    for (int o = 16; o > 0; o >>= 1) acc += __shfl_down_sync(0xffffffffu, acc, o);
    __shared__ float warpsum[8];
    if ((tid & 31) == 0) warpsum[tid >> 5] = acc;
    __syncthreads();
    if (tid < 8) {
        float v = warpsum[tid];
        #pragma unroll
        for (int o = 4; o > 0; o >>= 1) v += __shfl_down_sync(0xffu, v, o);
        if (tid == 0 && v != 0.f) atomicAdd(&g_loss, (double)v);
    }
}

__global__ void __launch_bounds__(256)
k_final(const float* __restrict__ mask,
        const int* __restrict__ regimes,
        int B, int n_regimes, float* __restrict__ out) {
    const int tid = threadIdx.x;
    float c = 0.f;
    for (int b = tid; b < B; b += 256) {
        int e = regimes[b];
        if (e < n_regimes) {
            int ec = e < 0 ? 0 : e;
            const float* mr = mask + (long long)ec * D;
            float s = 0.f;
            #pragma unroll 8
            for (int j = 0; j < D; j++) s += mr[j];
            c += s;
        }
    }
    #pragma unroll
    for (int o = 16; o > 0; o >>= 1) c += __shfl_down_sync(0xffffffffu, c, o);
    __shared__ float warpsum[8];
    if ((tid & 31) == 0) warpsum[tid >> 5] = c;
    __syncthreads();
    if (tid == 0) {
        float count = 0.f;
        #pragma unroll
        for (int w = 0; w < 8; w++) count += warpsum[w];
        float loss = (float)g_loss;
        out[0] = (count > 0.f) ? (loss / count) : loss;  // INTERVENTION_STRENGTH = 1.0
    }
}

extern "C" void kernel_launch(void* const* d_in, const int* in_sizes, int n_in,
                              void* d_out, int out_size) {
    const float* A    = (const float*)d_in[0];
    const float* mask = (const float*)d_in[1];
    const int*   reg  = (const int*)d_in[2];

    const int B = in_sizes[2];                 // 256
    const int n_regimes = in_sizes[1] / D;     // 16

    k_zero<<<1, 1>>>();
    dim3 grid(D / ROWS_PER_BLK, B);            // (8, 256) = 2048 blocks
    k_reduce<<<grid, 256>>>(A, mask, reg, n_regimes);
    k_final<<<1, 256>>>(mask, reg, B, n_regimes, (float*)d_out);
}